// round 4
// baseline (speedup 1.0000x reference)
#include <cuda_runtime.h>
#include <cuda_fp16.h>

#define D 64
#define NODES_CAP 50000
#define EDGES_CAP 1600000
#define SCAN_BLK 1024

// ---------------- scratch (static device globals; no allocation) ----------------
__device__ int   g_counts[NODES_CAP];
__device__ int   g_roff[NODES_CAP + 1];
__device__ int   g_cursor[NODES_CAP];
__device__ int   g_bsum[64];
__device__ int   g_scan_done;
__device__ float g_wsum[NODES_CAP];
__device__ int2  g_edge[EDGES_CAP];                       // (src, float_as_int(w))
__device__ float g_agg[NODES_CAP * D];                    // fp32 aggregation result
__device__ __align__(128) __half2 g_xh[NODES_CAP * 32];   // fp16 feature rows for gather

// ---------------- fused init + degree histogram ----------------
// thread i: (a) convert feature pair i to fp16 + write hidden = x*t0
//           (b) count edge i's dst
__global__ void k_init_count(const float* __restrict__ x, const float* __restrict__ temp,
                             const int* __restrict__ dst,
                             float* __restrict__ hidden, int nd2, int n_nodes, int E) {
    int i = blockIdx.x * blockDim.x + threadIdx.x;
    if (i == 0) g_scan_done = 0;
    if (i < nd2) {
        float t0 = __ldg(&temp[0]);
        float2 v = ((const float2*)x)[i];
        g_xh[i] = __floats2half2_rn(v.x, v.y);
        ((float2*)hidden)[i] = make_float2(v.x * t0, v.y * t0);
    }
    if (i < n_nodes) g_counts[i] = 0;
    __threadfence();   // counts zeroed before any atomics from other threads? (see grid-order note)
    if (i < E) atomicAdd(&g_counts[__ldg(&dst[i])], 1);
}

// NOTE: the zero + atomic in one kernel is racy across blocks. Safe variant below:
// we zero counts from the SAME thread range that atomics touch only after a grid-wide
// sync, which we don't have. So instead: zero in a tiny separate kernel is required.
// -> keep a dedicated zero kernel (cheap) and count in init kernel.
__global__ void k_zero(int n_nodes) {
    int i = blockIdx.x * blockDim.x + threadIdx.x;
    if (i < n_nodes) g_counts[i] = 0;
    if (i == 0) g_scan_done = 0;
}

__global__ void k_initcnt(const float* __restrict__ x, const float* __restrict__ temp,
                          const int* __restrict__ dst,
                          float* __restrict__ hidden, int nd2, int E) {
    int i = blockIdx.x * blockDim.x + threadIdx.x;
    if (i < nd2) {
        float t0 = __ldg(&temp[0]);
        float2 v = ((const float2*)x)[i];
        g_xh[i] = __floats2half2_rn(v.x, v.y);
        ((float2*)hidden)[i] = make_float2(v.x * t0, v.y * t0);
    }
    if (i < E) atomicAdd(&g_counts[__ldg(&dst[i])], 1);
}

// ---------------- scan1 + folded block-sum scan (last-block pattern) ----------------
__global__ void k_scan1(int N, int nb) {
    __shared__ int s[SCAN_BLK];
    __shared__ int is_last;
    int tid = threadIdx.x;
    int i = blockIdx.x * SCAN_BLK + tid;
    int v = (i < N) ? g_counts[i] : 0;
    s[tid] = v;
    __syncthreads();
    for (int off = 1; off < SCAN_BLK; off <<= 1) {
        int t = (tid >= off) ? s[tid - off] : 0;
        __syncthreads();
        s[tid] += t;
        __syncthreads();
    }
    if (i < N) g_roff[i] = s[tid] - v;          // block-local exclusive prefix
    if (tid == SCAN_BLK - 1) g_bsum[blockIdx.x] = s[tid];
    // last block to finish performs the exclusive scan of g_bsum
    __threadfence();
    if (tid == 0) is_last = (atomicAdd(&g_scan_done, 1) == nb - 1);
    __syncthreads();
    if (is_last && tid < 32) {
        int lane = tid;
        int v0 = (lane < nb) ? g_bsum[lane] : 0;
        int v1 = (lane + 32 < nb) ? g_bsum[lane + 32] : 0;
        int s0 = v0;
        #pragma unroll
        for (int off = 1; off < 32; off <<= 1) {
            int t = __shfl_up_sync(0xffffffffu, s0, off);
            if (lane >= off) s0 += t;
        }
        int tot0 = __shfl_sync(0xffffffffu, s0, 31);
        int s1 = v1;
        #pragma unroll
        for (int off = 1; off < 32; off <<= 1) {
            int t = __shfl_up_sync(0xffffffffu, s1, off);
            if (lane >= off) s1 += t;
        }
        if (lane < nb) g_bsum[lane] = s0 - v0;
        if (lane + 32 < nb) g_bsum[lane + 32] = tot0 + s1 - v1;
    }
}

__global__ void k_scan3(int N, int E) {
    int i = blockIdx.x * blockDim.x + threadIdx.x;
    if (i < N) {
        int r = g_roff[i] + g_bsum[i / SCAN_BLK];
        g_roff[i] = r;
        g_cursor[i] = r;
    }
    if (i == 0) g_roff[N] = E;
}

// ---------------- CSR fill: edges sorted by dst, (src,w) interleaved ----------------
__global__ void k_fill(const int* __restrict__ src, const int* __restrict__ dst,
                       const float* __restrict__ w, int E) {
    int e = blockIdx.x * blockDim.x + threadIdx.x;
    if (e < E) {
        int p = atomicAdd(&g_cursor[__ldg(&dst[e])], 1);
        g_edge[p] = make_int2(__ldg(&src[e]), __float_as_int(__ldg(&w[e])));
    }
}

// ---------------- SpMM: one warp per dst node, fp16 gather, fp32 accumulate ----------------
// agg[n] = sum over in-edges e of x[src_e] * w_e ; optionally also wsum[n] = sum w_e
__global__ void k_spmm(int N, int store_wsum) {
    int warp = (blockIdx.x * blockDim.x + threadIdx.x) >> 5;
    int lane = threadIdx.x & 31;
    if (warp >= N) return;
    int beg = __ldg(&g_roff[warp]);
    int end = __ldg(&g_roff[warp + 1]);
    float2 acc0 = make_float2(0.f, 0.f);
    float2 acc1 = make_float2(0.f, 0.f);
    float ws = 0.f;
    int e = beg;
    // head: align e to even index for int4 (16B) edge loads
    if ((e & 1) && e < end) {
        int2 ee = __ldg(&g_edge[e]);
        float wt = __int_as_float(ee.y);
        ws += wt;
        float2 f = __half22float2(__ldg(&g_xh[ee.x * 32 + lane]));
        acc0.x = fmaf(f.x, wt, acc0.x);
        acc0.y = fmaf(f.y, wt, acc0.y);
        e++;
    }
    for (; e + 8 <= end; e += 8) {
        const int4* p = (const int4*)&g_edge[e];   // 16B-aligned (e even)
        int4 q0 = __ldg(&p[0]);
        int4 q1 = __ldg(&p[1]);
        int4 q2 = __ldg(&p[2]);
        int4 q3 = __ldg(&p[3]);
        __half2 v0 = __ldg(&g_xh[q0.x * 32 + lane]);
        __half2 v1 = __ldg(&g_xh[q0.z * 32 + lane]);
        __half2 v2 = __ldg(&g_xh[q1.x * 32 + lane]);
        __half2 v3 = __ldg(&g_xh[q1.z * 32 + lane]);
        __half2 v4 = __ldg(&g_xh[q2.x * 32 + lane]);
        __half2 v5 = __ldg(&g_xh[q2.z * 32 + lane]);
        __half2 v6 = __ldg(&g_xh[q3.x * 32 + lane]);
        __half2 v7 = __ldg(&g_xh[q3.z * 32 + lane]);
        float w0 = __int_as_float(q0.y), w1 = __int_as_float(q0.w);
        float w2 = __int_as_float(q1.y), w3 = __int_as_float(q1.w);
        float w4 = __int_as_float(q2.y), w5 = __int_as_float(q2.w);
        float w6 = __int_as_float(q3.y), w7 = __int_as_float(q3.w);
        ws += (w0 + w1) + (w2 + w3) + (w4 + w5) + (w6 + w7);
        float2 f;
        f = __half22float2(v0); acc0.x = fmaf(f.x, w0, acc0.x); acc0.y = fmaf(f.y, w0, acc0.y);
        f = __half22float2(v1); acc1.x = fmaf(f.x, w1, acc1.x); acc1.y = fmaf(f.y, w1, acc1.y);
        f = __half22float2(v2); acc0.x = fmaf(f.x, w2, acc0.x); acc0.y = fmaf(f.y, w2, acc0.y);
        f = __half22float2(v3); acc1.x = fmaf(f.x, w3, acc1.x); acc1.y = fmaf(f.y, w3, acc1.y);
        f = __half22float2(v4); acc0.x = fmaf(f.x, w4, acc0.x); acc0.y = fmaf(f.y, w4, acc0.y);
        f = __half22float2(v5); acc1.x = fmaf(f.x, w5, acc1.x); acc1.y = fmaf(f.y, w5, acc1.y);
        f = __half22float2(v6); acc0.x = fmaf(f.x, w6, acc0.x); acc0.y = fmaf(f.y, w6, acc0.y);
        f = __half22float2(v7); acc1.x = fmaf(f.x, w7, acc1.x); acc1.y = fmaf(f.y, w7, acc1.y);
    }
    for (; e < end; e++) {
        int2 ee = __ldg(&g_edge[e]);
        float wt = __int_as_float(ee.y);
        ws += wt;
        float2 f = __half22float2(__ldg(&g_xh[ee.x * 32 + lane]));
        acc0.x = fmaf(f.x, wt, acc0.x);
        acc0.y = fmaf(f.y, wt, acc0.y);
    }
    acc0.x += acc1.x;
    acc0.y += acc1.y;
    ((float2*)g_agg)[warp * 32 + lane] = acc0;
    if (store_wsum && lane == 0) g_wsum[warp] = ws;
}

// ---------------- fused GEMM + bias*wsum + relu + hidden accumulation ----------------
// xn[n,o] = relu( sum_d agg[n,d]*W[o,d] + b[o]*wsum[n] )  -> stored fp16 in g_xh
// hidden[n,o] += xn[n,o] * temp[li+1]
__global__ void k_gemm(const float* __restrict__ Wl, const float* __restrict__ bl,
                       const float* __restrict__ temp, int li,
                       float* __restrict__ hidden, int N) {
    __shared__ __align__(16) float As[64][68];   // As[d][n]
    __shared__ __align__(16) float Bs[64][68];   // Bs[d][o]
    int tid = threadIdx.x;
    int bn = blockIdx.x * 64;
    float t = __ldg(&temp[li + 1]);

    for (int idx = tid; idx < 4096; idx += 256) {
        int o = idx >> 6, d = idx & 63;
        Bs[d][o] = __ldg(&Wl[o * 64 + d]);
    }
    for (int idx = tid; idx < 4096; idx += 256) {
        int n = idx >> 6, d = idx & 63;
        int node = bn + n;
        As[d][n] = (node < N) ? g_agg[node * 64 + d] : 0.f;
    }
    __syncthreads();

    int tx = tid & 15;          // output-column tile
    int ty = tid >> 4;          // node tile
    int o0 = tx * 4, n0 = ty * 4;

    float acc[4][4] = {};
    #pragma unroll
    for (int k = 0; k < 64; k++) {
        float4 a = *(const float4*)&As[k][n0];
        float4 b = *(const float4*)&Bs[k][o0];
        acc[0][0] = fmaf(a.x, b.x, acc[0][0]); acc[0][1] = fmaf(a.x, b.y, acc[0][1]);
        acc[0][2] = fmaf(a.x, b.z, acc[0][2]); acc[0][3] = fmaf(a.x, b.w, acc[0][3]);
        acc[1][0] = fmaf(a.y, b.x, acc[1][0]); acc[1][1] = fmaf(a.y, b.y, acc[1][1]);
        acc[1][2] = fmaf(a.y, b.z, acc[1][2]); acc[1][3] = fmaf(a.y, b.w, acc[1][3]);
        acc[2][0] = fmaf(a.z, b.x, acc[2][0]); acc[2][1] = fmaf(a.z, b.y, acc[2][1]);
        acc[2][2] = fmaf(a.z, b.z, acc[2][2]); acc[2][3] = fmaf(a.z, b.w, acc[2][3]);
        acc[3][0] = fmaf(a.w, b.x, acc[3][0]); acc[3][1] = fmaf(a.w, b.y, acc[3][1]);
        acc[3][2] = fmaf(a.w, b.z, acc[3][2]); acc[3][3] = fmaf(a.w, b.w, acc[3][3]);
    }

    float4 bo = *(const float4*)&bl[o0];
    #pragma unroll
    for (int i = 0; i < 4; i++) {
        int node = bn + n0 + i;
        if (node >= N) continue;
        float ws = g_wsum[node];
        float4 r;
        r.x = fmaxf(fmaf(bo.x, ws, acc[i][0]), 0.f);
        r.y = fmaxf(fmaf(bo.y, ws, acc[i][1]), 0.f);
        r.z = fmaxf(fmaf(bo.z, ws, acc[i][2]), 0.f);
        r.w = fmaxf(fmaf(bo.w, ws, acc[i][3]), 0.f);
        g_xh[node * 32 + (o0 >> 1) + 0] = __floats2half2_rn(r.x, r.y);
        g_xh[node * 32 + (o0 >> 1) + 1] = __floats2half2_rn(r.z, r.w);
        float4 h = *(float4*)&hidden[node * 64 + o0];
        h.x = fmaf(r.x, t, h.x);
        h.y = fmaf(r.y, t, h.y);
        h.z = fmaf(r.z, t, h.z);
        h.w = fmaf(r.w, t, h.w);
        *(float4*)&hidden[node * 64 + o0] = h;
    }
}

extern "C" void kernel_launch(void* const* d_in, const int* in_sizes, int n_in,
                              void* d_out, int out_size) {
    const float* x    = (const float*)d_in[0];
    const float* w    = (const float*)d_in[1];
    const float* W    = (const float*)d_in[2];
    const float* b    = (const float*)d_in[3];
    const float* temp = (const float*)d_in[4];
    const int*   src  = (const int*)d_in[5];
    const int*   dst  = (const int*)d_in[6];
    float* hidden = (float*)d_out;

    int nd = in_sizes[0];          // N * D
    int N  = nd / D;
    int E  = in_sizes[1];
    int L  = in_sizes[3] / D;
    int nd2 = nd / 2;

    k_zero<<<(N + 255) / 256, 256>>>(N);
    int mx = (E > nd2) ? E : nd2;
    k_initcnt<<<(mx + 255) / 256, 256>>>(x, temp, dst, hidden, nd2, E);
    int nb = (N + SCAN_BLK - 1) / SCAN_BLK;
    k_scan1<<<nb, SCAN_BLK>>>(N, nb);
    k_scan3<<<(N + 255) / 256, 256>>>(N, E);
    k_fill<<<(E + 255) / 256, 256>>>(src, dst, w, E);

    int spmm_blocks = (N + 7) / 8;            // 8 warps (nodes) per 256-thread block
    int gemm_blocks = (N + 63) / 64;
    for (int i = 0; i < L; i++) {
        k_spmm<<<spmm_blocks, 256>>>(N, (i == 0) ? 1 : 0);
        k_gemm<<<gemm_blocks, 256>>>(W + i * D * D, b + i * D, temp, i, hidden, N);
    }
}